// round 3
// baseline (speedup 1.0000x reference)
#include <cuda_runtime.h>

// DCTExtractor: gray = 0.299R+0.587G+0.114B; per 8x8 block: D @ blk @ D^T, * mask.
// x: (B,3,512,512) fp32; dct: (8,8); mask: (8,8); out: (B,1,512,512) fp32.
// HBM-bound: 201MB read + 67MB write. One CTA = one (batch, 8-row strip).

#define HW 512

__global__ __launch_bounds__(256)
void dct_extract_kernel(const float* __restrict__ x,
                        const float* __restrict__ dct,
                        const float* __restrict__ mask,
                        float* __restrict__ out)
{
    __shared__ float gray_s[8][HW];
    __shared__ float tmp_s[8][HW];
    __shared__ float D_s[8][8];
    __shared__ float M_s[8][8];

    const int tid  = threadIdx.x;
    const int strip = blockIdx.x;          // 0..63 (8-row strip)
    const int b     = blockIdx.y;          // batch
    const int rowbase = strip * 8;

    if (tid < 64) {
        D_s[tid >> 3][tid & 7] = dct[tid];
        M_s[tid >> 3][tid & 7] = mask[tid];
    }

    // ---- Load 8x512 of R,G,B (float4, coalesced), fuse grayscale into smem ----
    const size_t img = (size_t)b * 3 * HW * HW;
    const size_t plane = (size_t)HW * HW;
#pragma unroll
    for (int i = 0; i < 4; i++) {
        int f  = tid + i * 256;            // 0..1023 float4 slots
        int r  = f >> 7;                   // row 0..7
        int c4 = (f & 127) << 2;           // col 0..508 step 4
        size_t base = img + (size_t)(rowbase + r) * HW + c4;
        float4 R = *reinterpret_cast<const float4*>(x + base);
        float4 G = *reinterpret_cast<const float4*>(x + base + plane);
        float4 Bl = *reinterpret_cast<const float4*>(x + base + 2 * plane);
        float4 g;
        g.x = 0.299f * R.x + 0.587f * G.x + 0.114f * Bl.x;
        g.y = 0.299f * R.y + 0.587f * G.y + 0.114f * Bl.y;
        g.z = 0.299f * R.z + 0.587f * G.z + 0.114f * Bl.z;
        g.w = 0.299f * R.w + 0.587f * G.w + 0.114f * Bl.w;
        *reinterpret_cast<float4*>(&gray_s[r][c4]) = g;
    }
    __syncthreads();

    // ---- Stage 1: tmp = D @ gray  (one thread per column; conflict-free) ----
#pragma unroll
    for (int rep = 0; rep < 2; rep++) {
        int c = tid + rep * 256;           // 0..511
        float g[8];
#pragma unroll
        for (int j = 0; j < 8; j++) g[j] = gray_s[j][c];
#pragma unroll
        for (int i = 0; i < 8; i++) {
            float s = 0.f;
#pragma unroll
            for (int j = 0; j < 8; j++) s += D_s[i][j] * g[j];
            tmp_s[i][c] = s;
        }
    }
    __syncthreads();

    // ---- Stage 2: out = tmp @ D^T, apply mask, coalesced float4 stores ----
#pragma unroll
    for (int rep = 0; rep < 2; rep++) {
        int w   = tid + rep * 256;         // 0..511
        int row = w >> 6;                  // 0..7 (row within block)
        int blk = w & 63;                  // 8x8 block index along width
        float t[8];
#pragma unroll
        for (int k = 0; k < 8; k++) t[k] = tmp_s[row][blk * 8 + k];
        float o[8];
#pragma unroll
        for (int l = 0; l < 8; l++) {
            float s = 0.f;
#pragma unroll
            for (int k = 0; k < 8; k++) s += t[k] * D_s[l][k];
            o[l] = s * M_s[row][l];
        }
        size_t obase = ((size_t)b * HW + rowbase + row) * HW + blk * 8;
        *reinterpret_cast<float4*>(out + obase)     = make_float4(o[0], o[1], o[2], o[3]);
        *reinterpret_cast<float4*>(out + obase + 4) = make_float4(o[4], o[5], o[6], o[7]);
    }
}

extern "C" void kernel_launch(void* const* d_in, const int* in_sizes, int n_in,
                              void* d_out, int out_size)
{
    const float* x    = (const float*)d_in[0];
    const float* dct  = (const float*)d_in[1];
    const float* mask = (const float*)d_in[2];
    float* out = (float*)d_out;

    const int B = in_sizes[0] / (3 * HW * HW);   // 64
    dim3 grid(HW / 8, B);                         // (64, B)
    dct_extract_kernel<<<grid, 256>>>(x, dct, mask, out);
}

// round 6
// speedup vs baseline: 1.0007x; 1.0007x over previous
#include <cuda_runtime.h>

// DCTExtractor: gray = .299R+.587G+.114B; per 8x8 block: D @ blk @ D^T, * mask.
// x: (B,3,512,512) fp32 -> out: (B,1,512,512) fp32. Pure HBM-bound (268 MB traffic).
//
// v2: row-DCT fused into load phase (registers), butterfly halves FMA+regs,
// padded smem staging (SPAD=76) for conflict-free transpose, 1 sync, occ 4 CTA/SM.

#define HW 512
#define SPAD 76   // floats per 8x8 block in staging; 76 = conflict-free transpose

__global__ __launch_bounds__(256, 4)
void dct_extract_kernel(const float* __restrict__ x,
                        const float* __restrict__ dct,
                        const float* __restrict__ mask,
                        float* __restrict__ out)
{
    __shared__ float s[64 * SPAD];     // 19456 B staging (row-transformed blocks)
    __shared__ float Dh_s[8][4];       // D[l][k], k=0..3 (butterfly half)
    __shared__ float M_s[64];

    const int tid = threadIdx.x;
    const int rowbase = blockIdx.x * 8;
    const int b = blockIdx.y;

    if (tid < 64) {
        M_s[tid] = mask[tid];
        if ((tid & 7) < 4) Dh_s[tid >> 3][tid & 7] = dct[tid];
    }
    __syncthreads();

    const size_t img   = (size_t)b * 3 * HW * HW;
    const size_t plane = (size_t)HW * HW;

    // ---- Step A: load + grayscale + row-direction DCT (all in registers) ----
    // unit u: r = row-in-strip (0..7), blk = 8x8 block along width (0..63).
    // Warp = same r, 32 consecutive blks -> contiguous 1024B per channel.
#pragma unroll
    for (int rep = 0; rep < 2; rep++) {
        const int u   = tid + rep * 256;
        const int r   = u >> 6;
        const int blk = u & 63;
        const float* p0 = x + img + (size_t)(rowbase + r) * HW + blk * 8;

        float4 R0 = *reinterpret_cast<const float4*>(p0);
        float4 R1 = *reinterpret_cast<const float4*>(p0 + 4);
        float4 G0 = *reinterpret_cast<const float4*>(p0 + plane);
        float4 G1 = *reinterpret_cast<const float4*>(p0 + plane + 4);
        float4 B0 = *reinterpret_cast<const float4*>(p0 + 2 * plane);
        float4 B1 = *reinterpret_cast<const float4*>(p0 + 2 * plane + 4);

        float g[8];
        g[0] = fmaf(0.299f, R0.x, fmaf(0.587f, G0.x, 0.114f * B0.x));
        g[1] = fmaf(0.299f, R0.y, fmaf(0.587f, G0.y, 0.114f * B0.y));
        g[2] = fmaf(0.299f, R0.z, fmaf(0.587f, G0.z, 0.114f * B0.z));
        g[3] = fmaf(0.299f, R0.w, fmaf(0.587f, G0.w, 0.114f * B0.w));
        g[4] = fmaf(0.299f, R1.x, fmaf(0.587f, G1.x, 0.114f * B1.x));
        g[5] = fmaf(0.299f, R1.y, fmaf(0.587f, G1.y, 0.114f * B1.y));
        g[6] = fmaf(0.299f, R1.z, fmaf(0.587f, G1.z, 0.114f * B1.z));
        g[7] = fmaf(0.299f, R1.w, fmaf(0.587f, G1.w, 0.114f * B1.w));

        // Butterfly: D[l][7-k] = (-1)^l D[l][k]
        const float e0 = g[0] + g[7], e1 = g[1] + g[6], e2 = g[2] + g[5], e3 = g[3] + g[4];
        const float o0 = g[0] - g[7], o1 = g[1] - g[6], o2 = g[2] - g[5], o3 = g[3] - g[4];

        float v[8];
#pragma unroll
        for (int h = 0; h < 4; h++) {
            const int le = 2 * h, lo = 2 * h + 1;
            v[le] = fmaf(Dh_s[le][0], e0, fmaf(Dh_s[le][1], e1,
                    fmaf(Dh_s[le][2], e2, Dh_s[le][3] * e3)));
            v[lo] = fmaf(Dh_s[lo][0], o0, fmaf(Dh_s[lo][1], o1,
                    fmaf(Dh_s[lo][2], o2, Dh_s[lo][3] * o3)));
        }

        float* sp = s + blk * SPAD + r * 8;
        *reinterpret_cast<float4*>(sp)     = make_float4(v[0], v[1], v[2], v[3]);
        *reinterpret_cast<float4*>(sp + 4) = make_float4(v[4], v[5], v[6], v[7]);
    }
    __syncthreads();

    // ---- Step B: column-direction DCT + mask + coalesced scalar stores ----
    // unit u: l = column-in-block (0..7), blk (0..63). Warp spans 4 blks x 8 l.
    // LDS banks: (12*blk + 8*p + l) mod 32 -> conflict-free.
#pragma unroll
    for (int rep = 0; rep < 2; rep++) {
        const int u   = tid + rep * 256;
        const int l   = u & 7;
        const int blk = u >> 3;
        const float* sp = s + blk * SPAD + l;

        float t[8];
#pragma unroll
        for (int p = 0; p < 8; p++) t[p] = sp[p * 8];

        const float e0 = t[0] + t[7], e1 = t[1] + t[6], e2 = t[2] + t[5], e3 = t[3] + t[4];
        const float o0 = t[0] - t[7], o1 = t[1] - t[6], o2 = t[2] - t[5], o3 = t[3] - t[4];

        float* op = out + ((size_t)b * HW + rowbase) * HW + blk * 8 + l;
#pragma unroll
        for (int h = 0; h < 4; h++) {
            const int ie = 2 * h, io = 2 * h + 1;
            float ae = fmaf(Dh_s[ie][0], e0, fmaf(Dh_s[ie][1], e1,
                       fmaf(Dh_s[ie][2], e2, Dh_s[ie][3] * e3)));
            float ao = fmaf(Dh_s[io][0], o0, fmaf(Dh_s[io][1], o1,
                       fmaf(Dh_s[io][2], o2, Dh_s[io][3] * o3)));
            op[(size_t)ie * HW] = ae * M_s[ie * 8 + l];
            op[(size_t)io * HW] = ao * M_s[io * 8 + l];
        }
    }
}

extern "C" void kernel_launch(void* const* d_in, const int* in_sizes, int n_in,
                              void* d_out, int out_size)
{
    const float* x    = (const float*)d_in[0];
    const float* dct  = (const float*)d_in[1];
    const float* mask = (const float*)d_in[2];
    float* out = (float*)d_out;

    const int B = in_sizes[0] / (3 * HW * HW);
    dim3 grid(HW / 8, B);
    dct_extract_kernel<<<grid, 256>>>(x, dct, mask, out);
}

// round 7
// speedup vs baseline: 1.0498x; 1.0491x over previous
#include <cuda_runtime.h>

// DCTExtractor: gray = .299R+.587G+.114B; per 8x8 block: D @ blk @ D^T, * mask.
// x: (B,3,512,512) fp32 -> out: (B,1,512,512) fp32. HBM-bound (268 MB min traffic).
//
// v3: persistent grid-stride (296 CTAs x 512 thr), software-pipelined: next
// tile's LDGs issued before current tile's smem/store phase, so DRAM stays
// busy across __syncthreads. Streaming cache hints (no reuse, 268MB > L2).

#define HW 512
#define SPAD 76   // floats per 8x8 block in staging; conflict-free transpose

__global__ __launch_bounds__(512, 2)
void dct_extract_kernel(const float* __restrict__ x,
                        const float* __restrict__ dct,
                        const float* __restrict__ mask,
                        float* __restrict__ out,
                        int ntiles)
{
    __shared__ float s[64 * SPAD];     // 19456 B staging (row-transformed blocks)
    __shared__ float Dh_s[8][4];       // D[l][k], k=0..3 (butterfly half)
    __shared__ float M_s[64];

    const int tid = threadIdx.x;
    if (tid < 64) {
        M_s[tid] = mask[tid];
        if ((tid & 7) < 4) Dh_s[tid >> 3][tid & 7] = dct[tid];
    }
    __syncthreads();

    const size_t plane = (size_t)HW * HW;
    const int stride = gridDim.x;

    // Step-A unit coords: r = row-in-strip, blkA = block along width.
    const int rA   = tid >> 6;
    const int blkA = tid & 63;
    // Step-B unit coords: l = column-in-block, blkB = block along width.
    const int lB   = tid & 7;
    const int blkB = tid >> 3;

    int t = blockIdx.x;

    // ---- Prologue: load tile t (coalesced float4 x 6, streaming) ----
    float4 R0, R1, G0, G1, B0, B1;
    {
        const int b = t >> 6, rowbase = (t & 63) << 3;
        const float* p0 = x + (size_t)b * 3 * plane + (size_t)(rowbase + rA) * HW + blkA * 8;
        R0 = __ldcs(reinterpret_cast<const float4*>(p0));
        R1 = __ldcs(reinterpret_cast<const float4*>(p0 + 4));
        G0 = __ldcs(reinterpret_cast<const float4*>(p0 + plane));
        G1 = __ldcs(reinterpret_cast<const float4*>(p0 + plane + 4));
        B0 = __ldcs(reinterpret_cast<const float4*>(p0 + 2 * plane));
        B1 = __ldcs(reinterpret_cast<const float4*>(p0 + 2 * plane + 4));
    }

    while (true) {
        // ---- Grayscale (consumes raw regs) ----
        float g[8];
        g[0] = fmaf(0.299f, R0.x, fmaf(0.587f, G0.x, 0.114f * B0.x));
        g[1] = fmaf(0.299f, R0.y, fmaf(0.587f, G0.y, 0.114f * B0.y));
        g[2] = fmaf(0.299f, R0.z, fmaf(0.587f, G0.z, 0.114f * B0.z));
        g[3] = fmaf(0.299f, R0.w, fmaf(0.587f, G0.w, 0.114f * B0.w));
        g[4] = fmaf(0.299f, R1.x, fmaf(0.587f, G1.x, 0.114f * B1.x));
        g[5] = fmaf(0.299f, R1.y, fmaf(0.587f, G1.y, 0.114f * B1.y));
        g[6] = fmaf(0.299f, R1.z, fmaf(0.587f, G1.z, 0.114f * B1.z));
        g[7] = fmaf(0.299f, R1.w, fmaf(0.587f, G1.w, 0.114f * B1.w));

        // ---- Prefetch next tile (covers the entire store phase + syncs) ----
        const int t_next = t + stride;
        const bool more = (t_next < ntiles);
        if (more) {
            const int bn = t_next >> 6, rbn = (t_next & 63) << 3;
            const float* pn = x + (size_t)bn * 3 * plane + (size_t)(rbn + rA) * HW + blkA * 8;
            R0 = __ldcs(reinterpret_cast<const float4*>(pn));
            R1 = __ldcs(reinterpret_cast<const float4*>(pn + 4));
            G0 = __ldcs(reinterpret_cast<const float4*>(pn + plane));
            G1 = __ldcs(reinterpret_cast<const float4*>(pn + plane + 4));
            B0 = __ldcs(reinterpret_cast<const float4*>(pn + 2 * plane));
            B1 = __ldcs(reinterpret_cast<const float4*>(pn + 2 * plane + 4));
        }

        // ---- Row-direction DCT (butterfly), stage into padded smem ----
        {
            const float e0 = g[0] + g[7], e1 = g[1] + g[6], e2 = g[2] + g[5], e3 = g[3] + g[4];
            const float o0 = g[0] - g[7], o1 = g[1] - g[6], o2 = g[2] - g[5], o3 = g[3] - g[4];
            float v[8];
#pragma unroll
            for (int h = 0; h < 4; h++) {
                const int le = 2 * h, lo = 2 * h + 1;
                v[le] = fmaf(Dh_s[le][0], e0, fmaf(Dh_s[le][1], e1,
                        fmaf(Dh_s[le][2], e2, Dh_s[le][3] * e3)));
                v[lo] = fmaf(Dh_s[lo][0], o0, fmaf(Dh_s[lo][1], o1,
                        fmaf(Dh_s[lo][2], o2, Dh_s[lo][3] * o3)));
            }
            float* sp = s + blkA * SPAD + rA * 8;
            *reinterpret_cast<float4*>(sp)     = make_float4(v[0], v[1], v[2], v[3]);
            *reinterpret_cast<float4*>(sp + 4) = make_float4(v[4], v[5], v[6], v[7]);
        }
        __syncthreads();

        // ---- Column-direction DCT + mask + coalesced streaming stores ----
        {
            const float* sp = s + blkB * SPAD + lB;
            float tt[8];
#pragma unroll
            for (int p = 0; p < 8; p++) tt[p] = sp[p * 8];

            const float e0 = tt[0] + tt[7], e1 = tt[1] + tt[6], e2 = tt[2] + tt[5], e3 = tt[3] + tt[4];
            const float o0 = tt[0] - tt[7], o1 = tt[1] - tt[6], o2 = tt[2] - tt[5], o3 = tt[3] - tt[4];

            const int b = t >> 6, rowbase = (t & 63) << 3;
            float* op = out + ((size_t)b * HW + rowbase) * HW + blkB * 8 + lB;
#pragma unroll
            for (int h = 0; h < 4; h++) {
                const int ie = 2 * h, io = 2 * h + 1;
                float ae = fmaf(Dh_s[ie][0], e0, fmaf(Dh_s[ie][1], e1,
                           fmaf(Dh_s[ie][2], e2, Dh_s[ie][3] * e3)));
                float ao = fmaf(Dh_s[io][0], o0, fmaf(Dh_s[io][1], o1,
                           fmaf(Dh_s[io][2], o2, Dh_s[io][3] * o3)));
                __stcs(op + (size_t)ie * HW, ae * M_s[ie * 8 + lB]);
                __stcs(op + (size_t)io * HW, ao * M_s[io * 8 + lB]);
            }
        }

        if (!more) break;
        __syncthreads();        // protect smem before next iteration's STS
        t = t_next;
    }
}

extern "C" void kernel_launch(void* const* d_in, const int* in_sizes, int n_in,
                              void* d_out, int out_size)
{
    const float* x    = (const float*)d_in[0];
    const float* dct  = (const float*)d_in[1];
    const float* mask = (const float*)d_in[2];
    float* out = (float*)d_out;

    const int B = in_sizes[0] / (3 * HW * HW);
    const int ntiles = B * (HW / 8);           // 4096 for B=64
    int grid = 2 * 148;                        // 2 CTAs/SM resident, persistent
    if (grid > ntiles) grid = ntiles;
    dct_extract_kernel<<<grid, 512>>>(x, dct, mask, out, ntiles);
}

// round 8
// speedup vs baseline: 1.0861x; 1.0346x over previous
#include <cuda_runtime.h>

// DCTExtractor: gray = .299R+.587G+.114B; per 8x8 block: D @ blk @ D^T, * mask.
// x: (B,3,512,512) fp32 -> out: (B,1,512,512) fp32. HBM-bound (268 MB min traffic).
//
// v3: persistent grid-stride (296 CTAs x 512 thr), software-pipelined: next
// tile's LDGs issued before current tile's smem/store phase, so DRAM stays
// busy across __syncthreads. Streaming cache hints (no reuse, 268MB > L2).

#define HW 512
#define SPAD 76   // floats per 8x8 block in staging; conflict-free transpose

__global__ __launch_bounds__(512, 2)
void dct_extract_kernel(const float* __restrict__ x,
                        const float* __restrict__ dct,
                        const float* __restrict__ mask,
                        float* __restrict__ out,
                        int ntiles)
{
    __shared__ float s[64 * SPAD];     // 19456 B staging (row-transformed blocks)
    __shared__ float Dh_s[8][4];       // D[l][k], k=0..3 (butterfly half)
    __shared__ float M_s[64];

    const int tid = threadIdx.x;
    if (tid < 64) {
        M_s[tid] = mask[tid];
        if ((tid & 7) < 4) Dh_s[tid >> 3][tid & 7] = dct[tid];
    }
    __syncthreads();

    const size_t plane = (size_t)HW * HW;
    const int stride = gridDim.x;

    // Step-A unit coords: r = row-in-strip, blkA = block along width.
    const int rA   = tid >> 6;
    const int blkA = tid & 63;
    // Step-B unit coords: l = column-in-block, blkB = block along width.
    const int lB   = tid & 7;
    const int blkB = tid >> 3;

    int t = blockIdx.x;

    // ---- Prologue: load tile t (coalesced float4 x 6, streaming) ----
    float4 R0, R1, G0, G1, B0, B1;
    {
        const int b = t >> 6, rowbase = (t & 63) << 3;
        const float* p0 = x + (size_t)b * 3 * plane + (size_t)(rowbase + rA) * HW + blkA * 8;
        R0 = __ldcs(reinterpret_cast<const float4*>(p0));
        R1 = __ldcs(reinterpret_cast<const float4*>(p0 + 4));
        G0 = __ldcs(reinterpret_cast<const float4*>(p0 + plane));
        G1 = __ldcs(reinterpret_cast<const float4*>(p0 + plane + 4));
        B0 = __ldcs(reinterpret_cast<const float4*>(p0 + 2 * plane));
        B1 = __ldcs(reinterpret_cast<const float4*>(p0 + 2 * plane + 4));
    }

    while (true) {
        // ---- Grayscale (consumes raw regs) ----
        float g[8];
        g[0] = fmaf(0.299f, R0.x, fmaf(0.587f, G0.x, 0.114f * B0.x));
        g[1] = fmaf(0.299f, R0.y, fmaf(0.587f, G0.y, 0.114f * B0.y));
        g[2] = fmaf(0.299f, R0.z, fmaf(0.587f, G0.z, 0.114f * B0.z));
        g[3] = fmaf(0.299f, R0.w, fmaf(0.587f, G0.w, 0.114f * B0.w));
        g[4] = fmaf(0.299f, R1.x, fmaf(0.587f, G1.x, 0.114f * B1.x));
        g[5] = fmaf(0.299f, R1.y, fmaf(0.587f, G1.y, 0.114f * B1.y));
        g[6] = fmaf(0.299f, R1.z, fmaf(0.587f, G1.z, 0.114f * B1.z));
        g[7] = fmaf(0.299f, R1.w, fmaf(0.587f, G1.w, 0.114f * B1.w));

        // ---- Prefetch next tile (covers the entire store phase + syncs) ----
        const int t_next = t + stride;
        const bool more = (t_next < ntiles);
        if (more) {
            const int bn = t_next >> 6, rbn = (t_next & 63) << 3;
            const float* pn = x + (size_t)bn * 3 * plane + (size_t)(rbn + rA) * HW + blkA * 8;
            R0 = __ldcs(reinterpret_cast<const float4*>(pn));
            R1 = __ldcs(reinterpret_cast<const float4*>(pn + 4));
            G0 = __ldcs(reinterpret_cast<const float4*>(pn + plane));
            G1 = __ldcs(reinterpret_cast<const float4*>(pn + plane + 4));
            B0 = __ldcs(reinterpret_cast<const float4*>(pn + 2 * plane));
            B1 = __ldcs(reinterpret_cast<const float4*>(pn + 2 * plane + 4));
        }

        // ---- Row-direction DCT (butterfly), stage into padded smem ----
        {
            const float e0 = g[0] + g[7], e1 = g[1] + g[6], e2 = g[2] + g[5], e3 = g[3] + g[4];
            const float o0 = g[0] - g[7], o1 = g[1] - g[6], o2 = g[2] - g[5], o3 = g[3] - g[4];
            float v[8];
#pragma unroll
            for (int h = 0; h < 4; h++) {
                const int le = 2 * h, lo = 2 * h + 1;
                v[le] = fmaf(Dh_s[le][0], e0, fmaf(Dh_s[le][1], e1,
                        fmaf(Dh_s[le][2], e2, Dh_s[le][3] * e3)));
                v[lo] = fmaf(Dh_s[lo][0], o0, fmaf(Dh_s[lo][1], o1,
                        fmaf(Dh_s[lo][2], o2, Dh_s[lo][3] * o3)));
            }
            float* sp = s + blkA * SPAD + rA * 8;
            *reinterpret_cast<float4*>(sp)     = make_float4(v[0], v[1], v[2], v[3]);
            *reinterpret_cast<float4*>(sp + 4) = make_float4(v[4], v[5], v[6], v[7]);
        }
        __syncthreads();

        // ---- Column-direction DCT + mask + coalesced streaming stores ----
        {
            const float* sp = s + blkB * SPAD + lB;
            float tt[8];
#pragma unroll
            for (int p = 0; p < 8; p++) tt[p] = sp[p * 8];

            const float e0 = tt[0] + tt[7], e1 = tt[1] + tt[6], e2 = tt[2] + tt[5], e3 = tt[3] + tt[4];
            const float o0 = tt[0] - tt[7], o1 = tt[1] - tt[6], o2 = tt[2] - tt[5], o3 = tt[3] - tt[4];

            const int b = t >> 6, rowbase = (t & 63) << 3;
            float* op = out + ((size_t)b * HW + rowbase) * HW + blkB * 8 + lB;
#pragma unroll
            for (int h = 0; h < 4; h++) {
                const int ie = 2 * h, io = 2 * h + 1;
                float ae = fmaf(Dh_s[ie][0], e0, fmaf(Dh_s[ie][1], e1,
                           fmaf(Dh_s[ie][2], e2, Dh_s[ie][3] * e3)));
                float ao = fmaf(Dh_s[io][0], o0, fmaf(Dh_s[io][1], o1,
                           fmaf(Dh_s[io][2], o2, Dh_s[io][3] * o3)));
                __stcs(op + (size_t)ie * HW, ae * M_s[ie * 8 + lB]);
                __stcs(op + (size_t)io * HW, ao * M_s[io * 8 + lB]);
            }
        }

        if (!more) break;
        __syncthreads();        // protect smem before next iteration's STS
        t = t_next;
    }
}

extern "C" void kernel_launch(void* const* d_in, const int* in_sizes, int n_in,
                              void* d_out, int out_size)
{
    const float* x    = (const float*)d_in[0];
    const float* dct  = (const float*)d_in[1];
    const float* mask = (const float*)d_in[2];
    float* out = (float*)d_out;

    const int B = in_sizes[0] / (3 * HW * HW);
    const int ntiles = B * (HW / 8);           // 4096 for B=64
    int grid = 2 * 148;                        // 2 CTAs/SM resident, persistent
    if (grid > ntiles) grid = ntiles;
    dct_extract_kernel<<<grid, 512>>>(x, dct, mask, out, ntiles);
}